// round 15
// baseline (speedup 1.0000x reference)
#include <cuda_runtime.h>
#include <cuda_bf16.h>
#include <cuda_fp16.h>
#include <math_constants.h>
#include <math.h>
#include <stdint.h>

#define BATCH 4
#define SEQ   4096
#define NPTS  (BATCH*SEQ)   // 16384
#define DIM   256
#define KNN   16

typedef __nv_bfloat16 bf16;

// ---------------- scratch ----------------
__device__ float g_feat[NPTS*DIM];
__device__ bf16  g_fhi[NPTS*DIM];      // bf16 feat (GEMM input)
__device__ __half g_f16[NPTS*DIM];     // fp16 feat (distance)
__device__ float g_sq[NPTS];
__device__ int   g_idx[NPTS*KNN];
__device__ bf16  g_h  [NPTS*DIM];
__device__ bf16  g_vf [NPTS*DIM];
__device__ bf16  g_qgb [NPTS*DIM];
__device__ bf16  g_kg1b[NPTS*DIM];
__device__ bf16  g_resb[NPTS*DIM];
// bf16 weights
__device__ bf16 g_fc1b[DIM*DIM], g_wqb[DIM*DIM], g_wkb[DIM*DIM], g_wvb[DIM*DIM];
__device__ bf16 g_g1b[DIM*DIM], g_g2b[DIM*DIM], g_fc2b[DIM*DIM];
__device__ bf16 g_wq1[DIM*DIM], g_wk1[DIM*DIM];   // composed wq@g1, wk@g1

// ---------------- helpers ----------------
__device__ __forceinline__ uint32_t smem_u32(const void* p) {
    return (uint32_t)__cvta_generic_to_shared(p);
}
__device__ __forceinline__ void ldsm_x4(uint32_t addr, uint32_t& r0, uint32_t& r1, uint32_t& r2, uint32_t& r3) {
    asm volatile("ldmatrix.sync.aligned.m8n8.x4.shared.b16 {%0,%1,%2,%3}, [%4];"
                 : "=r"(r0), "=r"(r1), "=r"(r2), "=r"(r3) : "r"(addr));
}
__device__ __forceinline__ void ldsm_x4_t(uint32_t addr, uint32_t& r0, uint32_t& r1, uint32_t& r2, uint32_t& r3) {
    asm volatile("ldmatrix.sync.aligned.m8n8.x4.trans.shared.b16 {%0,%1,%2,%3}, [%4];"
                 : "=r"(r0), "=r"(r1), "=r"(r2), "=r"(r3) : "r"(addr));
}
__device__ __forceinline__ void mma_bf16(float* c, const uint32_t* a, const uint32_t* b) {
    asm volatile("mma.sync.aligned.m16n8k16.row.col.f32.bf16.bf16.f32 "
                 "{%0,%1,%2,%3},{%4,%5,%6,%7},{%8,%9},{%0,%1,%2,%3};"
                 : "+f"(c[0]), "+f"(c[1]), "+f"(c[2]), "+f"(c[3])
                 : "r"(a[0]), "r"(a[1]), "r"(a[2]), "r"(a[3]), "r"(b[0]), "r"(b[1]));
}
__device__ __forceinline__ void mma_fp16(float* c, const uint32_t* a, const uint32_t* b) {
    asm volatile("mma.sync.aligned.m16n8k16.row.col.f32.f16.f16.f32 "
                 "{%0,%1,%2,%3},{%4,%5,%6,%7},{%8,%9},{%0,%1,%2,%3};"
                 : "+f"(c[0]), "+f"(c[1]), "+f"(c[2]), "+f"(c[3])
                 : "r"(a[0]), "r"(a[1]), "r"(a[2]), "r"(a[3]), "r"(b[0]), "r"(b[1]));
}
__device__ __forceinline__ void cp16(uint32_t saddr, const void* g) {
    asm volatile("cp.async.cg.shared.global [%0], [%1], 16;" :: "r"(saddr), "l"(g));
}
#define CP_COMMIT() asm volatile("cp.async.commit_group;")
#define CP_WAIT0()  asm volatile("cp.async.wait_group 0;")

// ---------------- weight conversion (all 7 in one launch) ----------------
struct CvtArgs { const float* s[7]; bf16* d[7]; };
__global__ void cvt_all_kernel(CvtArgs a) {
    int seg = blockIdx.x >> 6;
    int i = ((blockIdx.x & 63) * 256 + threadIdx.x) * 4;
    const float* s = a.s[seg];
    bf16* d = a.d[seg];
    float4 v = *(const float4*)(s + i);
    d[i+0] = __float2bfloat16_rn(v.x);
    d[i+1] = __float2bfloat16_rn(v.y);
    d[i+2] = __float2bfloat16_rn(v.z);
    d[i+3] = __float2bfloat16_rn(v.w);
}

// ---------------- prep ----------------
__global__ void prep_kernel(const float* __restrict__ x, float* __restrict__ pos_out) {
    int r = blockIdx.x;
    const float* xr = x + (size_t)r * (3 + DIM);
    int t = threadIdx.x;
    __shared__ float red[256];
    if (t < 3) pos_out[r*3 + t] = xr[t];
    float f = xr[3 + t];
    g_feat[(size_t)r*DIM + t] = f;
    g_fhi[(size_t)r*DIM + t] = __float2bfloat16_rn(f);
    g_f16[(size_t)r*DIM + t] = __float2half_rn(f);
    red[t] = f * f;
    __syncthreads();
    for (int s = 128; s > 0; s >>= 1) {
        if (t < s) red[t] += red[t + s];
        __syncthreads();
    }
    if (t == 0) g_sq[r] = red[0];
}

// ================= fused distance (fp16 mma.sync) + top-K, cp.async pipelined =================
// Grid (32, BATCH), 256 threads, ~199 KB smem (1 CTA/SM). Block owns 128 i-rows (A resident).
// Per j-tile, B (128x256) streams as two 128-wide k-chunks, double-buffered with cp.async:
// chunk s+1 loads from L2 while chunk s is in the MMA loop. Key = sq_j - 2*dot.
#define DT_A_LD     264
#define DT_B_LD     136
#define DT_B0_OFF   67584                       // 128*264*2
#define DT_B1_OFF   (DT_B0_OFF + 34816)         // 128*136*2
#define DT_SQ_OFF   (DT_B1_OFF + 34816)         // 137216
#define DT_SD_OFF   (DT_SQ_OFF + 512)           // 137728
#define DT_SD_LD    129
#define DT_SMEM_SZ  (DT_SD_OFF + 128*DT_SD_LD*4)   // 203776

__global__ void __launch_bounds__(256, 1)
dist_topk_kernel() {
    extern __shared__ char smem[];
    uint32_t sb = smem_u32(smem);
    __half* As = (__half*)smem;
    float* sq_s = (float*)(smem + DT_SQ_OFF);
    float* sd   = (float*)(smem + DT_SD_OFF);

    int t = threadIdx.x;
    int lane = t & 31, w = t >> 5;
    int wm = w & 3, wn = w >> 2;
    int b = blockIdx.y;
    int i0 = blockIdx.x * 128;

    const __half* F = g_f16 + (size_t)b * SEQ * DIM;
    const float* sqb = g_sq + (size_t)b * SEQ;

    // resident A strip: 128 x 256 fp16
    for (int idx = t; idx < 128 * 32; idx += 256) {
        int r = idx >> 5, c = (idx & 31) * 8;
        *(uint4*)(As + r * DT_A_LD + c) = *(const uint4*)(F + (size_t)(i0 + r) * 256 + c);
    }

    // per-thread running top-16 for row (t>>1), half (t&1)
    float tv[16]; int ti_[16];
#pragma unroll
    for (int n = 0; n < 16; n++) { tv[n] = CUDART_INF_F; ti_[n] = -1; }
    int srow = t >> 1, shalf = t & 1;
    const float* rowp = sd + srow * DT_SD_LD + shalf * 64;

    // chunk loader: step = jt*2 + k-chunk; buffer parity = step&1
#define DT_ISSUE(stp) do { \
        int _j0 = ((stp) >> 1) * 128, _kb = ((stp) & 1) * 128; \
        uint32_t _bb = sb + (((stp) & 1) ? DT_B1_OFF : DT_B0_OFF); \
        _Pragma("unroll") \
        for (int _q = 0; _q < 8; _q++) { \
            int _f = t + _q * 256; \
            int _r = _f >> 4, _c = (_f & 15) * 8; \
            cp16(_bb + (_r * DT_B_LD + _c) * 2, F + (size_t)(_j0 + _r) * 256 + _kb + _c); \
        } \
        CP_COMMIT(); \
    } while (0)

    DT_ISSUE(0);

    float acc[2][8][4];
#pragma unroll 1
    for (int step = 0; step < 64; step++) {
        int jt = step >> 1, chunk = step & 1;
        int j0 = jt * 128;
        if (chunk == 0) {
            if (t < 128) sq_s[t] = sqb[j0 + t];
#pragma unroll
            for (int mi = 0; mi < 2; mi++)
#pragma unroll
                for (int nj = 0; nj < 8; nj++)
#pragma unroll
                    for (int e = 0; e < 4; e++) acc[mi][nj][e] = 0.f;
        }
        CP_WAIT0();
        __syncthreads();
        if (step + 1 < 64) DT_ISSUE(step + 1);

        uint32_t bbase = sb + ((step & 1) ? DT_B1_OFF : DT_B0_OFF);
#pragma unroll
        for (int kb = 0; kb < 128; kb += 32) {
#pragma unroll
            for (int kk = 0; kk < 32; kk += 16) {
                uint32_t a[2][4], bfr[8][2];
#pragma unroll
                for (int mi = 0; mi < 2; mi++) {
                    uint32_t addr = sb + ((wm*32 + mi*16 + (lane & 15)) * DT_A_LD
                                          + chunk*128 + kb + kk + (lane >> 4) * 8) * 2;
                    ldsm_x4(addr, a[mi][0], a[mi][1], a[mi][2], a[mi][3]);
                }
#pragma unroll
                for (int g = 0; g < 4; g++) {
                    int nrow = wn*64 + g*16 + (lane & 7) + ((lane >> 4) << 3);
                    int ncol = kb + kk + ((lane >> 3) & 1) * 8;
                    uint32_t r0, r1, r2, r3;
                    ldsm_x4(bbase + (nrow * DT_B_LD + ncol) * 2, r0, r1, r2, r3);
                    bfr[g*2][0] = r0; bfr[g*2][1] = r1;
                    bfr[g*2+1][0] = r2; bfr[g*2+1][1] = r3;
                }
#pragma unroll
                for (int mi = 0; mi < 2; mi++)
#pragma unroll
                    for (int nj = 0; nj < 8; nj++)
                        mma_fp16(acc[mi][nj], a[mi], bfr[nj]);
            }
        }

        if (chunk == 1) {
            // write keys into sd (own-warp fragments)
#pragma unroll
            for (int mi = 0; mi < 2; mi++) {
                int r = wm*32 + mi*16 + (lane >> 2);
#pragma unroll
                for (int nj = 0; nj < 8; nj++) {
                    int c = wn*64 + nj*8 + (lane & 3) * 2;
                    float s0 = sq_s[c], s1 = sq_s[c + 1];
                    sd[r * DT_SD_LD + c]           = s0 - 2.f * acc[0+0][nj][0]*0.f - 2.f * acc[mi][nj][0];
                    sd[r * DT_SD_LD + c + 1]       = s1 - 2.f * acc[mi][nj][1];
                    sd[(r + 8) * DT_SD_LD + c]     = s0 - 2.f * acc[mi][nj][2];
                    sd[(r + 8) * DT_SD_LD + c + 1] = s1 - 2.f * acc[mi][nj][3];
                }
            }
            __syncthreads();
            // scan 64 keys of this thread's row-half
            int jbase = j0 + shalf * 64;
#pragma unroll 4
            for (int j = 0; j < 64; j++) {
                float d = rowp[j];
                if (d < tv[15]) {
                    float cv = d; int ci = jbase + j;
#pragma unroll
                    for (int n = 0; n < 16; n++) {
                        if (cv < tv[n]) {
                            float tvv = tv[n]; tv[n] = cv; cv = tvv;
                            int tii = ti_[n]; ti_[n] = ci; ci = tii;
                        }
                    }
                }
            }
            // no sync: next step's post-wait sync protects sd overwrite
        }
    }
#undef DT_ISSUE

    // merge both halves' lists via smem (keys in sd[row][0..31], ids at [32..63])
    __syncthreads();
#pragma unroll
    for (int n = 0; n < 16; n++) {
        sd[srow * DT_SD_LD + shalf * 16 + n] = tv[n];
        ((int*)sd)[srow * DT_SD_LD + 32 + shalf * 16 + n] = ti_[n];
    }
    __syncthreads();
    if (t < 128) {
        float mv[16]; int mid[16];
#pragma unroll
        for (int n = 0; n < 16; n++) { mv[n] = CUDART_INF_F; mid[n] = -1; }
#pragma unroll
        for (int p = 0; p < 32; p++) {
            float d = sd[t * DT_SD_LD + p];
            if (d < mv[15]) {
                float cv = d; int ci = ((int*)sd)[t * DT_SD_LD + 32 + p];
#pragma unroll
                for (int n = 0; n < 16; n++) {
                    if (cv < mv[n]) {
                        float tvv = mv[n]; mv[n] = cv; cv = tvv;
                        int tii = mid[n]; mid[n] = ci; ci = tii;
                    }
                }
            }
        }
        size_t base = ((size_t)b * SEQ + i0 + t) * 16;
#pragma unroll
        for (int n = 0; n < 16; n++) g_idx[base + n] = b * SEQ + mid[n];
    }
}

// ---------------- bf16 tensor-core GEMM: C[Mx256] = A[Mx256] @ W[256x256] ----------------
template<bool HAS_BIAS, bool HAS_ADD, bool OUT_BF16>
__global__ void __launch_bounds__(256)
mma_gemm(const bf16* __restrict__ Ag, const bf16* __restrict__ Wg,
         const float* __restrict__ bias, const float* __restrict__ addsrc,
         void* __restrict__ Cout) {
    __shared__ bf16 As[128][40];
    __shared__ bf16 Ws_[32][136];
    int t = threadIdx.x;
    int lane = t & 31, w = t >> 5;
    int wm = w & 3, wn = w >> 2;
    int m0 = blockIdx.x * 128;
    int n0 = blockIdx.y * 128;

    float acc[2][8][4];
#pragma unroll
    for (int mi = 0; mi < 2; mi++)
#pragma unroll
        for (int nj = 0; nj < 8; nj++)
#pragma unroll
            for (int e = 0; e < 4; e++) acc[mi][nj][e] = 0.f;

    for (int kb = 0; kb < 256; kb += 32) {
#pragma unroll
        for (int q = 0; q < 2; q++) {
            int flat = t * 2 + q;
            int row = flat >> 2, col = (flat & 3) * 8;
            *(uint4*)&As[row][col] = *(const uint4*)(Ag + ((size_t)(m0 + row) * 256 + kb + col));
        }
#pragma unroll
        for (int q = 0; q < 2; q++) {
            int flat = t * 2 + q;
            int row = flat >> 4, col = (flat & 15) * 8;
            *(uint4*)&Ws_[row][col] = *(const uint4*)(Wg + ((size_t)(kb + row) * 256 + n0 + col));
        }
        __syncthreads();
#pragma unroll
        for (int kk = 0; kk < 32; kk += 16) {
            uint32_t a[2][4], bfr[8][2];
#pragma unroll
            for (int mi = 0; mi < 2; mi++) {
                uint32_t addr = smem_u32(&As[wm*32 + mi*16 + (lane & 15)][kk + (lane >> 4) * 8]);
                ldsm_x4(addr, a[mi][0], a[mi][1], a[mi][2], a[mi][3]);
            }
#pragma unroll
            for (int g = 0; g < 4; g++) {
                uint32_t r0, r1, r2, r3;
                uint32_t addr = smem_u32(&Ws_[kk + (lane & 15)][wn*64 + g*16 + (lane >> 4) * 8]);
                ldsm_x4_t(addr, r0, r1, r2, r3);
                bfr[g*2][0] = r0; bfr[g*2][1] = r1;
                bfr[g*2+1][0] = r2; bfr[g*2+1][1] = r3;
            }
#pragma unroll
            for (int mi = 0; mi < 2; mi++)
#pragma unroll
                for (int nj = 0; nj < 8; nj++)
                    mma_bf16(acc[mi][nj], a[mi], bfr[nj]);
        }
        __syncthreads();
    }

#pragma unroll
    for (int mi = 0; mi < 2; mi++) {
#pragma unroll
        for (int nj = 0; nj < 8; nj++) {
            int r = m0 + wm*32 + mi*16 + (lane >> 2);
            int cc = n0 + wn*64 + nj*8 + (lane & 3) * 2;
            float v0 = acc[mi][nj][0], v1 = acc[mi][nj][1];
            float v2 = acc[mi][nj][2], v3 = acc[mi][nj][3];
            if (HAS_BIAS) {
                float b0 = bias[cc], b1 = bias[cc+1];
                v0 += b0; v1 += b1; v2 += b0; v3 += b1;
            }
            if (HAS_ADD) {
                v0 += addsrc[(size_t)r*256 + cc];     v1 += addsrc[(size_t)r*256 + cc + 1];
                v2 += addsrc[(size_t)(r+8)*256 + cc]; v3 += addsrc[(size_t)(r+8)*256 + cc + 1];
            }
            if (OUT_BF16) {
                bf16* C = (bf16*)Cout;
                __nv_bfloat162 o0, o1;
                o0.x = __float2bfloat16_rn(v0); o0.y = __float2bfloat16_rn(v1);
                o1.x = __float2bfloat16_rn(v2); o1.y = __float2bfloat16_rn(v3);
                *(__nv_bfloat162*)(C + (size_t)r*256 + cc) = o0;
                *(__nv_bfloat162*)(C + (size_t)(r+8)*256 + cc) = o1;
            } else {
                float* C = (float*)Cout;
                float2 o0 = {v0, v1}, o1 = {v2, v3};
                *(float2*)(C + (size_t)r*256 + cc) = o0;
                *(float2*)(C + (size_t)(r+8)*256 + cc) = o1;
            }
        }
    }
}

// ---------------- fused 3-projection GEMM: {vf, qg(+g1_b), kg1} = h @ {wv, wq1, wk1} ----------------
struct Proj3Args { const bf16* w[3]; bf16* d[3]; const float* bias; };
__global__ void __launch_bounds__(256)
mma_gemm_proj3(const bf16* __restrict__ Ag, Proj3Args pa) {
    __shared__ bf16 As[128][40];
    __shared__ bf16 Ws_[32][136];
    int t = threadIdx.x;
    int lane = t & 31, w = t >> 5;
    int wm = w & 3, wn = w >> 2;
    int m0 = blockIdx.x * 128;
    int wi = blockIdx.y >> 1;
    int n0 = (blockIdx.y & 1) * 128;
    const bf16* Wg = pa.w[wi];
    bf16* C = pa.d[wi];
    bool has_bias = (wi == 1);

    float acc[2][8][4];
#pragma unroll
    for (int mi = 0; mi < 2; mi++)
#pragma unroll
        for (int nj = 0; nj < 8; nj++)
#pragma unroll
            for (int e = 0; e < 4; e++) acc[mi][nj][e] = 0.f;

    for (int kb = 0; kb < 256; kb += 32) {
#pragma unroll
        for (int q = 0; q < 2; q++) {
            int flat = t * 2 + q;
            int row = flat >> 2, col = (flat & 3) * 8;
            *(uint4*)&As[row][col] = *(const uint4*)(Ag + ((size_t)(m0 + row) * 256 + kb + col));
        }
#pragma unroll
        for (int q = 0; q < 2; q++) {
            int flat = t * 2 + q;
            int row = flat >> 4, col = (flat & 15) * 8;
            *(uint4*)&Ws_[row][col] = *(const uint4*)(Wg + ((size_t)(kb + row) * 256 + n0 + col));
        }
        __syncthreads();
#pragma unroll
        for (int kk = 0; kk < 32; kk += 16) {
            uint32_t a[2][4], bfr[8][2];
#pragma unroll
            for (int mi = 0; mi < 2; mi++) {
                uint32_t addr = smem_u32(&As[wm*32 + mi*16 + (lane & 15)][kk + (lane >> 4) * 8]);
                ldsm_x4(addr, a[mi][0], a[mi][1], a[mi][2], a[mi][3]);
            }
#pragma unroll
            for (int g = 0; g < 4; g++) {
                uint32_t r0, r1, r2, r3;
                uint32_t addr = smem_u32(&Ws_[kk + (lane & 15)][wn*64 + g*16 + (lane >> 4) * 8]);
                ldsm_x4_t(addr, r0, r1, r2, r3);
                bfr[g*2][0] = r0; bfr[g*2][1] = r1;
                bfr[g*2+1][0] = r2; bfr[g*2+1][1] = r3;
            }
#pragma unroll
            for (int mi = 0; mi < 2; mi++)
#pragma unroll
                for (int nj = 0; nj < 8; nj++)
                    mma_bf16(acc[mi][nj], a[mi], bfr[nj]);
        }
        __syncthreads();
    }

#pragma unroll
    for (int mi = 0; mi < 2; mi++) {
#pragma unroll
        for (int nj = 0; nj < 8; nj++) {
            int r = m0 + wm*32 + mi*16 + (lane >> 2);
            int cc = n0 + wn*64 + nj*8 + (lane & 3) * 2;
            float v0 = acc[mi][nj][0], v1 = acc[mi][nj][1];
            float v2 = acc[mi][nj][2], v3 = acc[mi][nj][3];
            if (has_bias) {
                float b0 = pa.bias[cc], b1 = pa.bias[cc+1];
                v0 += b0; v1 += b1; v2 += b0; v3 += b1;
            }
            __nv_bfloat162 o0, o1;
            o0.x = __float2bfloat16_rn(v0); o0.y = __float2bfloat16_rn(v1);
            o1.x = __float2bfloat16_rn(v2); o1.y = __float2bfloat16_rn(v3);
            *(__nv_bfloat162*)(C + (size_t)r*256 + cc) = o0;
            *(__nv_bfloat162*)(C + (size_t)(r+8)*256 + cc) = o1;
        }
    }
}

// ---------------- fused attention v2: full R resident + cp.async double-buffered g2 ----------------
// smem: Rs [128][264] bf16 (67584) | Ws 2x[32][264] (16896 ea) | nbr 128 ints
#define AT_LD       264
#define AT_WS0_OFF  67584
#define AT_WS1_OFF  (AT_WS0_OFF + 16896)
#define AT_NBR_OFF  (AT_WS1_OFF + 16896)        // 101376
#define AT_SMEM_SZ  (AT_NBR_OFF + 512)          // 101888

__global__ void __launch_bounds__(512, 1)
attn_fused_kernel() {
    extern __shared__ char smem[];
    uint32_t sb = smem_u32(smem);
    bf16* Rs = (bf16*)smem;
    int* nbr = (int*)(smem + AT_NBR_OFF);

    int t = threadIdx.x;
    int lane = t & 31, w = t >> 5;
    int wm = w & 3, wn = w >> 2;
    int m0 = blockIdx.x * 128;

    if (t < 128) nbr[t] = g_idx[m0 + t];
    __syncthreads();

    // build full R tile: relu(qg[point] - kg1[neighbor]), 128 x 256
    int rrow = t >> 2;
    int cg4 = (t & 3) * 8;
    int pt_r = (m0 + rrow) >> 4;
    int nr_r = nbr[rrow];
    const uint4* qrow = (const uint4*)(g_qgb  + (size_t)pt_r * 256);
    const uint4* krow = (const uint4*)(g_kg1b + (size_t)nr_r * 256);
    __nv_bfloat162 z2 = __float2bfloat162_rn(0.f);
#pragma unroll
    for (int kb = 0; kb < 8; kb++) {
        int col = kb * 32 + cg4;
        uint4 qv = qrow[col >> 3];
        uint4 kv = krow[col >> 3];
        const __nv_bfloat162* qp = (const __nv_bfloat162*)&qv;
        const __nv_bfloat162* kp = (const __nv_bfloat162*)&kv;
        uint4 ov;
        __nv_bfloat162* op = (__nv_bfloat162*)&ov;
#pragma unroll
        for (int e = 0; e < 4; e++)
            op[e] = __hmax2(__hsub2(qp[e], kp[e]), z2);
        *(uint4*)(Rs + rrow * AT_LD + col) = ov;
    }

    // prefetch g2 chunk 0
#define AT_ISSUE(kbi) do { \
        uint32_t _wb = sb + (((kbi) & 1) ? AT_WS1_OFF : AT_WS0_OFF); \
        _Pragma("unroll") \
        for (int _q = 0; _q < 2; _q++) { \
            int _f = t * 2 + _q; \
            int _r = _f >> 5, _c = (_f & 31) * 8; \
            cp16(_wb + (_r * AT_LD + _c) * 2, g_g2b + (size_t)((kbi) * 32 + _r) * 256 + _c); \
        } \
        CP_COMMIT(); \
    } while (0)

    AT_ISSUE(0);

    float acc[2][8][4];
#pragma unroll
    for (int mi = 0; mi < 2; mi++)
#pragma unroll
        for (int nj = 0; nj < 8; nj++)
#pragma unroll
            for (int e = 0; e < 4; e++) acc[mi][nj][e] = 0.f;

#pragma unroll 1
    for (int kbi = 0; kbi < 8; kbi++) {
        CP_WAIT0();
        __syncthreads();            // Ws chunk ready; also covers Rs on first iter
        if (kbi < 7) AT_ISSUE(kbi + 1);

        uint32_t wbase = sb + ((kbi & 1) ? AT_WS1_OFF : AT_WS0_OFF);
#pragma unroll
        for (int kk = 0; kk < 32; kk += 16) {
            uint32_t a[2][4], bfr[8][2];
#pragma unroll
            for (int mi = 0; mi < 2; mi++) {
                uint32_t addr = sb + ((wm*32 + mi*16 + (lane & 15)) * AT_LD
                                      + kbi*32 + kk + (lane >> 4) * 8) * 2;
                ldsm_x4(addr, a[mi][0], a[mi][1], a[mi][2], a[mi][3]);
            }
#pragma unroll
            for (int g = 0; g < 4; g++) {
                uint32_t r0, r1, r2, r3;
                uint32_t addr = wbase + ((kk + (lane & 15)) * AT_LD
                                         + wn*64 + g*16 + (lane >> 4) * 8) * 2;
                ldsm_x4_t(addr, r0, r1, r2, r3);
                bfr[g*2][0] = r0; bfr[g*2][1] = r1;
                bfr[g*2+1][0] = r2; bfr[g*2+1][1] = r3;
            }
#pragma unroll
            for (int mi = 0; mi < 2; mi++)
#pragma unroll
                for (int nj = 0; nj < 8; nj++)
                    mma_bf16(acc[mi][nj], a[mi], bfr[nj]);
        }
    }
#undef AT_ISSUE

    // epilogue: softmax over the 16 rows of each m16 fragment + v-contraction
    const float inv = 0.0625f;
#pragma unroll
    for (int mi = 0; mi < 2; mi++) {
        int lrow = wm * 32 + mi * 16;
        int ptm = (m0 + lrow) >> 4;
        int nrA = nbr[lrow + (lane >> 2)];
        int nrB = nbr[lrow + 8 + (lane >> 2)];
#pragma unroll
        for (int nj = 0; nj < 8; nj++) {
            int cc = wn * 64 + nj * 8 + (lane & 3) * 2;
            float x0 = acc[mi][nj][0], x1 = acc[mi][nj][1];
            float x2 = acc[mi][nj][2], x3 = acc[mi][nj][3];
            float mA = fmaxf(x0, x2), mB = fmaxf(x1, x3);
#pragma unroll
            for (int off = 4; off <= 16; off <<= 1) {
                mA = fmaxf(mA, __shfl_xor_sync(0xffffffffu, mA, off));
                mB = fmaxf(mB, __shfl_xor_sync(0xffffffffu, mB, off));
            }
            float e0 = __expf((x0 - mA) * inv), e2 = __expf((x2 - mA) * inv);
            float e1 = __expf((x1 - mB) * inv), e3 = __expf((x3 - mB) * inv);
            __nv_bfloat162 vA = *(const __nv_bfloat162*)(g_vf + (size_t)nrA * 256 + cc);
            __nv_bfloat162 vB = *(const __nv_bfloat162*)(g_vf + (size_t)nrB * 256 + cc);
            float sA = e0 + e2, sB = e1 + e3;
            float wA = e0 * __bfloat162float(vA.x) + e2 * __bfloat162float(vB.x);
            float wB = e1 * __bfloat162float(vA.y) + e3 * __bfloat162float(vB.y);
#pragma unroll
            for (int off = 4; off <= 16; off <<= 1) {
                sA += __shfl_xor_sync(0xffffffffu, sA, off);
                sB += __shfl_xor_sync(0xffffffffu, sB, off);
                wA += __shfl_xor_sync(0xffffffffu, wA, off);
                wB += __shfl_xor_sync(0xffffffffu, wB, off);
            }
            if ((lane >> 2) == 0) {
                __nv_bfloat162 o;
                o.x = __float2bfloat16_rn(wA / sA);
                o.y = __float2bfloat16_rn(wB / sB);
                *(__nv_bfloat162*)(g_resb + (size_t)ptm * 256 + cc) = o;
            }
        }
    }
}

// ---------------- launch ----------------
extern "C" void kernel_launch(void* const* d_in, const int* in_sizes, int n_in,
                              void* d_out, int out_size) {
    const float* x     = (const float*)d_in[0];
    const float* fc1_w = (const float*)d_in[1];
    const float* fc1_b = (const float*)d_in[2];
    const float* fc2_w = (const float*)d_in[3];
    const float* fc2_b = (const float*)d_in[4];
    const float* wq_w  = (const float*)d_in[5];
    const float* wk_w  = (const float*)d_in[6];
    const float* wv_w  = (const float*)d_in[7];
    const float* g1_w  = (const float*)d_in[8];
    const float* g1_b  = (const float*)d_in[9];
    const float* g2_w  = (const float*)d_in[10];
    const float* g2_b  = (const float*)d_in[11];  (void)g2_b;
    float* out = (float*)d_out;

    bf16 *p_fc1b, *p_wqb, *p_wkb, *p_wvb, *p_g1b, *p_g2b, *p_fc2b, *p_wq1, *p_wk1;
    bf16 *p_fhi, *p_h, *p_vf, *p_qgb, *p_kg1b, *p_resb;
    float *p_feat;
    cudaGetSymbolAddress((void**)&p_fc1b, g_fc1b);
    cudaGetSymbolAddress((void**)&p_wqb,  g_wqb);
    cudaGetSymbolAddress((void**)&p_wkb,  g_wkb);
    cudaGetSymbolAddress((void**)&p_wvb,  g_wvb);
    cudaGetSymbolAddress((void**)&p_g1b,  g_g1b);
    cudaGetSymbolAddress((void**)&p_g2b,  g_g2b);
    cudaGetSymbolAddress((void**)&p_fc2b, g_fc2b);
    cudaGetSymbolAddress((void**)&p_wq1,  g_wq1);
    cudaGetSymbolAddress((void**)&p_wk1,  g_wk1);
    cudaGetSymbolAddress((void**)&p_fhi,  g_fhi);
    cudaGetSymbolAddress((void**)&p_h,    g_h);
    cudaGetSymbolAddress((void**)&p_vf,   g_vf);
    cudaGetSymbolAddress((void**)&p_qgb,  g_qgb);
    cudaGetSymbolAddress((void**)&p_kg1b, g_kg1b);
    cudaGetSymbolAddress((void**)&p_resb, g_resb);
    cudaGetSymbolAddress((void**)&p_feat, g_feat);

    static int s_init_done = 0;
    static cudaStream_t s1;
    static cudaEvent_t e0, e1;
    if (!s_init_done) {
        cudaFuncSetAttribute(dist_topk_kernel,
                             cudaFuncAttributeMaxDynamicSharedMemorySize, DT_SMEM_SZ);
        cudaFuncSetAttribute(attn_fused_kernel,
                             cudaFuncAttributeMaxDynamicSharedMemorySize, AT_SMEM_SZ);
        cudaStreamCreateWithFlags(&s1, cudaStreamNonBlocking);
        cudaEventCreateWithFlags(&e0, cudaEventDisableTiming);
        cudaEventCreateWithFlags(&e1, cudaEventDisableTiming);
        s_init_done = 1;
    }

    // prep first so dist can fork as early as possible
    prep_kernel<<<NPTS, 256>>>(x, out);

    // fork: distance + top-K on side stream
    cudaEventRecord(e0, 0);
    cudaStreamWaitEvent(s1, e0, 0);
    dist_topk_kernel<<<dim3(32, BATCH), 256, DT_SMEM_SZ, s1>>>();
    cudaEventRecord(e1, s1);

    // main stream: weight conversion + composed weights + h + 3 projections
    CvtArgs ca;
    ca.s[0] = fc1_w; ca.d[0] = p_fc1b;
    ca.s[1] = wq_w;  ca.d[1] = p_wqb;
    ca.s[2] = wk_w;  ca.d[2] = p_wkb;
    ca.s[3] = wv_w;  ca.d[3] = p_wvb;
    ca.s[4] = g1_w;  ca.d[4] = p_g1b;
    ca.s[5] = g2_w;  ca.d[5] = p_g2b;
    ca.s[6] = fc2_w; ca.d[6] = p_fc2b;
    cvt_all_kernel<<<7*64, 256>>>(ca);

    mma_gemm<false, false, true><<<dim3(2, 2), 256>>>(p_wqb, p_g1b, nullptr, nullptr, p_wq1);
    mma_gemm<false, false, true><<<dim3(2, 2), 256>>>(p_wkb, p_g1b, nullptr, nullptr, p_wk1);
    mma_gemm<true,  false, true><<<dim3(NPTS/128, 2), 256>>>(p_fhi, p_fc1b, fc1_b, nullptr, p_h);

    Proj3Args pa;
    pa.w[0] = p_wvb; pa.d[0] = p_vf;
    pa.w[1] = p_wq1; pa.d[1] = p_qgb;
    pa.w[2] = p_wk1; pa.d[2] = p_kg1b;
    pa.bias = g1_b;
    mma_gemm_proj3<<<dim3(NPTS/128, 6), 256>>>(p_h, pa);

    // join: attention tail needs g_idx
    cudaStreamWaitEvent(0, e1, 0);
    attn_fused_kernel<<<(NPTS*KNN)/128, 512, AT_SMEM_SZ>>>();

    // out = res@fc2 + fc2_b + feat
    mma_gemm<true, true, false><<<dim3(NPTS/128, 2), 256>>>(p_resb, p_fc2b, fc2_b, p_feat, out + (size_t)NPTS*3);
}